// round 14
// baseline (speedup 1.0000x reference)
#include <cuda_runtime.h>
#include <cstdint>

#define S_LEN 2048
#define HEADS 8
#define BATCH 2
#define DHEAD 128
#define BM 256
#define BN 64
#define NJT (S_LEN / BN)
#define THREADS 256

// smem: Q tf32 [256][512B]=128KB; K [64][512B] x2 bufs; V^T [128][256B] single
#define SM_Q 0
#define SM_K 131072  // + buf*32768
#define SM_V 196608
#define SMEM_TOTAL 229376

#define NROWS (BATCH * HEADS * S_LEN)

__device__ uint4 g_kt[NROWS * 32];                 // K tf32, [bh*2048+j][128]
__device__ uint4 g_vt[BATCH * HEADS * 8192 * 16];  // V^T tf32, [bh*128+d][2048]
__device__ float g_rnorm[HEADS * S_LEN];

__device__ __forceinline__ uint32_t smem_u32(const void* p) {
    uint32_t a;
    asm("{ .reg .u64 t; cvta.to.shared.u64 t, %1; cvt.u32.u64 %0, t; }" : "=r"(a) : "l"(p));
    return a;
}
__device__ __forceinline__ uint32_t f2tf(float f) {
    uint32_t r;
    asm("cvt.rna.tf32.f32 %0, %1;" : "=r"(r) : "f"(f));
    return r;
}
__device__ __forceinline__ void cpa16(uint32_t dst, const void* src) {
    asm volatile("cp.async.cg.shared.global [%0], [%1], 16;" :: "r"(dst), "l"(src));
}
__device__ __forceinline__ void ldmx4(uint32_t& r0, uint32_t& r1, uint32_t& r2, uint32_t& r3,
                                      uint32_t a) {
    asm volatile("ldmatrix.sync.aligned.m8n8.x4.shared.b16 {%0,%1,%2,%3}, [%4];"
                 : "=r"(r0), "=r"(r1), "=r"(r2), "=r"(r3) : "r"(a));
}
__device__ __forceinline__ void mmat(float* c, uint32_t a0, uint32_t a1, uint32_t a2,
                                     uint32_t a3, uint32_t b0, uint32_t b1) {
    asm volatile(
        "mma.sync.aligned.m16n8k8.row.col.f32.tf32.tf32.f32 "
        "{%0,%1,%2,%3},{%4,%5,%6,%7},{%8,%9},{%0,%1,%2,%3};"
        : "+f"(c[0]), "+f"(c[1]), "+f"(c[2]), "+f"(c[3])
        : "r"(a0), "r"(a1), "r"(a2), "r"(a3), "r"(b0), "r"(b1));
}

// ---------------- prep: K fp32 -> tf32 ----------------
__global__ void kcvt_kernel(const float* __restrict__ k) {
    int gid = blockIdx.x * 512 + threadIdx.x;
    float4 f = ((const float4*)k)[gid];
    ((uint4*)g_kt)[gid] = make_uint4(f2tf(f.x), f2tf(f.y), f2tf(f.z), f2tf(f.w));
}

// ---------------- prep: V fp32 -> tf32 transposed [bh][d][j] ----------------
__global__ void vtr_kernel(const float* __restrict__ v) {
    __shared__ uint32_t t[32][33];
    int bh = blockIdx.z, j0 = blockIdx.x * 32, d0 = blockIdx.y * 32;
    const float* src = v + ((size_t)bh * S_LEN + j0) * DHEAD + d0;
#pragma unroll
    for (int i = 0; i < 4; i++)
        t[threadIdx.y + i * 8][threadIdx.x] =
            f2tf(src[(threadIdx.y + i * 8) * DHEAD + threadIdx.x]);
    __syncthreads();
    uint32_t* dst = (uint32_t*)g_vt + ((size_t)bh * DHEAD + d0) * S_LEN + j0;
#pragma unroll
    for (int i = 0; i < 4; i++)
        dst[(threadIdx.y + i * 8) * S_LEN + threadIdx.x] = t[threadIdx.x][threadIdx.y + i * 8];
}

// ---------------- rnorm: rsqrt(sum_j omask[h,i,j]) ----------------
__global__ void rnorm_kernel(const float* __restrict__ omask) {
    int row = blockIdx.x;
    const float* p = omask + (size_t)row * S_LEN;
    float s = 0.f;
    for (int j = threadIdx.x * 4; j < S_LEN; j += 256 * 4) {
        float4 f = *(const float4*)(p + j);
        s += f.x + f.y + f.z + f.w;
    }
#pragma unroll
    for (int off = 16; off > 0; off >>= 1) s += __shfl_xor_sync(0xffffffffu, s, off);
    __shared__ float red[8];
    if ((threadIdx.x & 31) == 0) red[threadIdx.x >> 5] = s;
    __syncthreads();
    if (threadIdx.x == 0) {
        float t = 0.f;
#pragma unroll
        for (int i = 0; i < 8; i++) t += red[i];
        g_rnorm[row] = (t > 0.f) ? rsqrtf(t) : 0.f;
    }
}

__global__ __launch_bounds__(THREADS, 1)
void retention_mma_kernel(const float* __restrict__ q, const float* __restrict__ omask,
                          float* __restrict__ out) {
    extern __shared__ char smc[];
    const uint32_t su = smem_u32(smc);
    const int tid = threadIdx.x;
    const int wid = tid >> 5, lane = tid & 31;
    const int m0 = wid * 32;  // each warp: rows m0..m0+31, full width
    const int g = lane >> 2, c = lane & 3;

    const int it = blockIdx.x, h = blockIdx.y, b = blockIdx.z;
    const int i0 = it * BM;
    const size_t bh = (size_t)(b * HEADS + h);
    const float* qbase = q + (bh * S_LEN + i0) * DHEAD;
    const float* mbase = omask + ((size_t)h * S_LEN + i0) * S_LEN;
    const char* gkt = (const char*)g_kt + bh * (S_LEN * DHEAD * 4);
    const char* gvt = (const char*)g_vt + bh * (S_LEN * DHEAD * 4);

    // ---- issue K0 (buf0) + V0 via cp.async ----
#pragma unroll
    for (int i = 0; i < 8; i++) {
        int x = tid + i * THREADS;  // 0..2047
        int kr = x >> 5, kc = x & 31;
        cpa16(su + SM_K + kr * 512 + ((kc ^ (kr & 7)) << 4), gkt + (size_t)kr * 512 + kc * 16);
        int vr = x >> 4, vc = x & 15;
        cpa16(su + SM_V + vr * 256 + ((vc ^ (vr & 7)) << 4), gvt + (size_t)vr * 8192 + vc * 16);
    }
    asm volatile("cp.async.commit_group;" ::: "memory");

    // ---- Q tile [256x128] -> tf32 smem ----
#pragma unroll 4
    for (int i = 0; i < 32; i++) {
        int x = tid + i * THREADS;
        int r = x >> 5, ch = x & 31;
        float4 f = *(const float4*)(qbase + r * DHEAD + ch * 4);
        *(uint4*)(smc + SM_Q + r * 512 + ((ch ^ (r & 7)) << 4)) =
            make_uint4(f2tf(f.x), f2tf(f.y), f2tf(f.z), f2tf(f.w));
    }

    float rn[2][2];
#pragma unroll
    for (int mt = 0; mt < 2; mt++) {
        rn[mt][0] = g_rnorm[h * S_LEN + i0 + m0 + mt * 16 + g];
        rn[mt][1] = g_rnorm[h * S_LEN + i0 + m0 + mt * 16 + g + 8];
    }

    float oacc[2][16][4];
#pragma unroll
    for (int mt = 0; mt < 2; mt++)
#pragma unroll
        for (int nt = 0; nt < 16; nt++)
#pragma unroll
            for (int e = 0; e < 4; e++) oacc[mt][nt][e] = 0.f;

    const int lrow = lane & 7;
    const int acb = lane >> 4;        // A chunk sub (0..1)
    const int bcb = lane >> 3;        // B chunk sub (0..3)
    const int aro = lrow + ((lane >> 3) & 1) * 8;

    const int slo = (lane & ~3) | (c >> 1);
    const int shi = (lane & ~3) | ((c >> 1) + 2);
    const bool codd = (c & 1);

    for (int jt = 0; jt < NJT; jt++) {
        const int buf = jt & 1;

        // ---- issue next K into buf^1 ----
        if (jt + 1 < NJT) {
            const size_t krb = (size_t)(jt + 1) * BN * 512;
            const uint32_t sb = (buf ^ 1) * 32768;
#pragma unroll
            for (int i = 0; i < 8; i++) {
                int x = tid + i * THREADS;
                int kr = x >> 5, kc = x & 31;
                cpa16(su + SM_K + sb + kr * 512 + ((kc ^ (kr & 7)) << 4),
                      gkt + krb + (size_t)kr * 512 + kc * 16);
            }
        }
        asm volatile("cp.async.commit_group;" ::: "memory");

        // ---- mask prefetch (rn folded), m32 x j64 ----
        float2 mk0[2][8], mk1[2][8];
#pragma unroll
        for (int mt = 0; mt < 2; mt++) {
            const float* mp =
                mbase + (size_t)(m0 + mt * 16 + g) * S_LEN + jt * BN + c * 2;
#pragma unroll
            for (int nt = 0; nt < 8; nt++) {
                float2 t0 = *(const float2*)(mp + nt * 8);
                float2 t1 = *(const float2*)(mp + 8 * S_LEN + nt * 8);
                mk0[mt][nt] = make_float2(t0.x * rn[mt][0], t0.y * rn[mt][0]);
                mk1[mt][nt] = make_float2(t1.x * rn[mt][1], t1.y * rn[mt][1]);
            }
        }

        asm volatile("cp.async.wait_group 1;" ::: "memory");
        __syncthreads();  // K(jt), V(jt) visible; prev-iter reads done

        const uint32_t khb = su + SM_K + buf * 32768;
        const uint32_t vhb = su + SM_V;

        // ---- GEMM1: S[m32][j64] = Q @ K^T (tf32), K-frags shared across mt ----
        float sacc[2][8][4];
#pragma unroll
        for (int mt = 0; mt < 2; mt++)
#pragma unroll
            for (int nt = 0; nt < 8; nt++)
#pragma unroll
                for (int e = 0; e < 4; e++) sacc[mt][nt][e] = 0.f;
#pragma unroll
        for (int ksp = 0; ksp < 8; ksp++) {
            uint32_t a[2][8];
#pragma unroll
            for (int mt = 0; mt < 2; mt++) {
                int qrow = m0 + mt * 16 + aro;
                ldmx4(a[mt][0], a[mt][1], a[mt][2], a[mt][3],
                      su + SM_Q + qrow * 512 + (((4 * ksp + acb) ^ (qrow & 7)) << 4));
                ldmx4(a[mt][4], a[mt][5], a[mt][6], a[mt][7],
                      su + SM_Q + qrow * 512 + (((4 * ksp + 2 + acb) ^ (qrow & 7)) << 4));
            }
#pragma unroll
            for (int np = 0; np < 8; np++) {
                int krow = np * 8 + lrow;
                uint32_t b0, b1, b2, b3;
                ldmx4(b0, b1, b2, b3,
                      khb + krow * 512 + (((4 * ksp + bcb) ^ (krow & 7)) << 4));
#pragma unroll
                for (int mt = 0; mt < 2; mt++) {
                    mmat(sacc[mt][np], a[mt][0], a[mt][1], a[mt][2], a[mt][3], b0, b1);
                    mmat(sacc[mt][np], a[mt][4], a[mt][5], a[mt][6], a[mt][7], b2, b3);
                }
            }
        }

        // ---- epilogue: sacc *= mask * rn ----
#pragma unroll
        for (int mt = 0; mt < 2; mt++)
#pragma unroll
            for (int nt = 0; nt < 8; nt++) {
                sacc[mt][nt][0] *= mk0[mt][nt].x;
                sacc[mt][nt][1] *= mk0[mt][nt].y;
                sacc[mt][nt][2] *= mk1[mt][nt].x;
                sacc[mt][nt][3] *= mk1[mt][nt].y;
            }

        // ---- GEMM2: O[m32][d128] += S @ V, V-frags shared across mt ----
#pragma unroll
        for (int ktp = 0; ktp < 4; ktp++) {
            uint32_t af[2][2][4];
#pragma unroll
            for (int mt = 0; mt < 2; mt++)
#pragma unroll
                for (int kk = 0; kk < 2; kk++) {
                    const float* s4 = sacc[mt][2 * ktp + kk];
                    float v0 = __shfl_sync(0xffffffffu, s4[0], slo);
                    float v1 = __shfl_sync(0xffffffffu, s4[1], slo);
                    float w0 = __shfl_sync(0xffffffffu, s4[0], shi);
                    float w1 = __shfl_sync(0xffffffffu, s4[1], shi);
                    float x0 = __shfl_sync(0xffffffffu, s4[2], slo);
                    float x1 = __shfl_sync(0xffffffffu, s4[3], slo);
                    float y0 = __shfl_sync(0xffffffffu, s4[2], shi);
                    float y1 = __shfl_sync(0xffffffffu, s4[3], shi);
                    af[mt][kk][0] = f2tf(codd ? v1 : v0);
                    af[mt][kk][1] = f2tf(codd ? x1 : x0);
                    af[mt][kk][2] = f2tf(codd ? w1 : w0);
                    af[mt][kk][3] = f2tf(codd ? y1 : y0);
                }
#pragma unroll
            for (int n8 = 0; n8 < 16; n8++) {
                int vrow = n8 * 8 + lrow;
                uint32_t b0, b1, b2, b3;
                ldmx4(b0, b1, b2, b3,
                      vhb + vrow * 256 + (((4 * ktp + bcb) ^ (vrow & 7)) << 4));
#pragma unroll
                for (int mt = 0; mt < 2; mt++) {
                    mmat(oacc[mt][n8], af[mt][0][0], af[mt][0][1], af[mt][0][2],
                         af[mt][0][3], b0, b1);
                    mmat(oacc[mt][n8], af[mt][1][0], af[mt][1][1], af[mt][1][2],
                         af[mt][1][3], b2, b3);
                }
            }
        }

        // ---- rotate single V buffer ----
        __syncthreads();  // all V reads done
        if (jt + 1 < NJT) {
            const size_t vcbyte = (size_t)(jt + 1) * 256;
#pragma unroll
            for (int i = 0; i < 8; i++) {
                int x = tid + i * THREADS;
                int vr = x >> 4, vc = x & 15;
                cpa16(su + SM_V + vr * 256 + ((vc ^ (vr & 7)) << 4),
                      gvt + (size_t)vr * 8192 + vcbyte + vc * 16);
            }
        }
        asm volatile("cp.async.commit_group;" ::: "memory");
    }

    // ---- RMSNorm (warp-local rows) + store ----
#pragma unroll
    for (int mt = 0; mt < 2; mt++) {
        float p0 = 0.f, p1 = 0.f;
#pragma unroll
        for (int nt = 0; nt < 16; nt++) {
            p0 += oacc[mt][nt][0] * oacc[mt][nt][0] + oacc[mt][nt][1] * oacc[mt][nt][1];
            p1 += oacc[mt][nt][2] * oacc[mt][nt][2] + oacc[mt][nt][3] * oacc[mt][nt][3];
        }
        p0 += __shfl_xor_sync(0xffffffffu, p0, 1);
        p0 += __shfl_xor_sync(0xffffffffu, p0, 2);
        p1 += __shfl_xor_sync(0xffffffffu, p1, 1);
        p1 += __shfl_xor_sync(0xffffffffu, p1, 2);
        float sc0 = rsqrtf(p0 * (1.f / 128.f) + 1e-6f);
        float sc1 = rsqrtf(p1 * (1.f / 128.f) + 1e-6f);
        float* o0 = out + (bh * S_LEN + i0 + m0 + mt * 16 + g) * DHEAD + c * 2;
        float* o1 = o0 + 8 * DHEAD;
#pragma unroll
        for (int nt = 0; nt < 16; nt++) {
            *(float2*)(o0 + nt * 8) = make_float2(oacc[mt][nt][0] * sc0, oacc[mt][nt][1] * sc0);
            *(float2*)(o1 + nt * 8) = make_float2(oacc[mt][nt][2] * sc1, oacc[mt][nt][3] * sc1);
        }
    }
}

extern "C" void kernel_launch(void* const* d_in, const int* in_sizes, int n_in,
                              void* d_out, int out_size) {
    const float* q = (const float*)d_in[0];
    const float* k = (const float*)d_in[1];
    const float* v = (const float*)d_in[2];
    const float* omask = (const float*)d_in[3];
    float* out = (float*)d_out;

    cudaFuncSetAttribute(retention_mma_kernel, cudaFuncAttributeMaxDynamicSharedMemorySize,
                         SMEM_TOTAL);

    kcvt_kernel<<<NROWS * DHEAD / (512 * 4), 512>>>(k);
    vtr_kernel<<<dim3(S_LEN / 32, DHEAD / 32, BATCH * HEADS), dim3(32, 8)>>>(v);
    rnorm_kernel<<<HEADS * S_LEN, 256>>>(omask);
    retention_mma_kernel<<<dim3(S_LEN / BM, HEADS, BATCH), THREADS, SMEM_TOTAL>>>(
        q, omask, out);
}

// round 15
// speedup vs baseline: 1.0194x; 1.0194x over previous
#include <cuda_runtime.h>
#include <cstdint>

#define S_LEN 2048
#define HEADS 8
#define BATCH 2
#define DHEAD 128
#define BM 256
#define BN 64
#define NJT (S_LEN / BN)
#define THREADS 256

// smem: Q tf32 [256][512B]=128KB; K [64][512B] x2 bufs; V^T [128][256B] single
#define SM_Q 0
#define SM_K 131072  // + buf*32768
#define SM_V 196608
#define SMEM_TOTAL 229376

#define NROWS (BATCH * HEADS * S_LEN)

__device__ uint4 g_kt[NROWS * 32];                 // K tf32, [bh*2048+j][128]
__device__ uint4 g_vt[BATCH * HEADS * 8192 * 16];  // V^T tf32, [bh*128+d][2048]

__device__ __forceinline__ uint32_t smem_u32(const void* p) {
    uint32_t a;
    asm("{ .reg .u64 t; cvta.to.shared.u64 t, %1; cvt.u32.u64 %0, t; }" : "=r"(a) : "l"(p));
    return a;
}
__device__ __forceinline__ uint32_t f2tf(float f) {
    uint32_t r;
    asm("cvt.rna.tf32.f32 %0, %1;" : "=r"(r) : "f"(f));
    return r;
}
__device__ __forceinline__ void cpa16(uint32_t dst, const void* src) {
    asm volatile("cp.async.cg.shared.global [%0], [%1], 16;" :: "r"(dst), "l"(src));
}
__device__ __forceinline__ void ldmx4(uint32_t& r0, uint32_t& r1, uint32_t& r2, uint32_t& r3,
                                      uint32_t a) {
    asm volatile("ldmatrix.sync.aligned.m8n8.x4.shared.b16 {%0,%1,%2,%3}, [%4];"
                 : "=r"(r0), "=r"(r1), "=r"(r2), "=r"(r3) : "r"(a));
}
__device__ __forceinline__ void mmat(float* c, uint32_t a0, uint32_t a1, uint32_t a2,
                                     uint32_t a3, uint32_t b0, uint32_t b1) {
    asm volatile(
        "mma.sync.aligned.m16n8k8.row.col.f32.tf32.tf32.f32 "
        "{%0,%1,%2,%3},{%4,%5,%6,%7},{%8,%9},{%0,%1,%2,%3};"
        : "+f"(c[0]), "+f"(c[1]), "+f"(c[2]), "+f"(c[3])
        : "r"(a0), "r"(a1), "r"(a2), "r"(a3), "r"(b0), "r"(b1));
}

// ---------------- prep: K fp32 -> tf32 ----------------
__global__ void kcvt_kernel(const float* __restrict__ k) {
    int gid = blockIdx.x * 512 + threadIdx.x;
    float4 f = ((const float4*)k)[gid];
    ((uint4*)g_kt)[gid] = make_uint4(f2tf(f.x), f2tf(f.y), f2tf(f.z), f2tf(f.w));
}

// ---------------- prep: V fp32 -> tf32 transposed [bh][d][j] ----------------
__global__ void vtr_kernel(const float* __restrict__ v) {
    __shared__ uint32_t t[32][33];
    int bh = blockIdx.z, j0 = blockIdx.x * 32, d0 = blockIdx.y * 32;
    const float* src = v + ((size_t)bh * S_LEN + j0) * DHEAD + d0;
#pragma unroll
    for (int i = 0; i < 4; i++)
        t[threadIdx.y + i * 8][threadIdx.x] =
            f2tf(src[(threadIdx.y + i * 8) * DHEAD + threadIdx.x]);
    __syncthreads();
    uint32_t* dst = (uint32_t*)g_vt + ((size_t)bh * DHEAD + d0) * S_LEN + j0;
#pragma unroll
    for (int i = 0; i < 4; i++)
        dst[(threadIdx.y + i * 8) * S_LEN + threadIdx.x] = t[threadIdx.x][threadIdx.y + i * 8];
}

__global__ __launch_bounds__(THREADS, 1)
void retention_mma_kernel(const float* __restrict__ q, const float* __restrict__ omask,
                          float* __restrict__ out) {
    extern __shared__ char smc[];
    const uint32_t su = smem_u32(smc);
    const int tid = threadIdx.x;
    const int wid = tid >> 5, lane = tid & 31;
    const int m0 = wid * 32;  // each warp: rows m0..m0+31, full width
    const int g = lane >> 2, c = lane & 3;

    const int it = blockIdx.x, h = blockIdx.y, b = blockIdx.z;
    const int i0 = it * BM;
    const size_t bh = (size_t)(b * HEADS + h);
    const float* qbase = q + (bh * S_LEN + i0) * DHEAD;
    const float* mbase = omask + ((size_t)h * S_LEN + i0) * S_LEN;
    const char* gkt = (const char*)g_kt + bh * (S_LEN * DHEAD * 4);
    const char* gvt = (const char*)g_vt + bh * (S_LEN * DHEAD * 4);

    // ---- issue K0 (buf0) + V0 via cp.async ----
#pragma unroll
    for (int i = 0; i < 8; i++) {
        int x = tid + i * THREADS;  // 0..2047
        int kr = x >> 5, kc = x & 31;
        cpa16(su + SM_K + kr * 512 + ((kc ^ (kr & 7)) << 4), gkt + (size_t)kr * 512 + kc * 16);
        int vr = x >> 4, vc = x & 15;
        cpa16(su + SM_V + vr * 256 + ((vc ^ (vr & 7)) << 4), gvt + (size_t)vr * 8192 + vc * 16);
    }
    asm volatile("cp.async.commit_group;" ::: "memory");

    // ---- Q tile [256x128] -> tf32 smem ----
#pragma unroll 4
    for (int i = 0; i < 32; i++) {
        int x = tid + i * THREADS;
        int r = x >> 5, ch = x & 31;
        float4 f = *(const float4*)(qbase + r * DHEAD + ch * 4);
        *(uint4*)(smc + SM_Q + r * 512 + ((ch ^ (r & 7)) << 4)) =
            make_uint4(f2tf(f.x), f2tf(f.y), f2tf(f.z), f2tf(f.w));
    }

    float oacc[2][16][4];
#pragma unroll
    for (int mt = 0; mt < 2; mt++)
#pragma unroll
        for (int nt = 0; nt < 16; nt++)
#pragma unroll
            for (int e = 0; e < 4; e++) oacc[mt][nt][e] = 0.f;

    const int lrow = lane & 7;
    const int acb = lane >> 4;  // A chunk sub (0..1)
    const int bcb = lane >> 3;  // B chunk sub (0..3)
    const int aro = lrow + ((lane >> 3) & 1) * 8;

    const int slo = (lane & ~3) | (c >> 1);
    const int shi = (lane & ~3) | ((c >> 1) + 2);
    const bool codd = (c & 1);

    for (int jt = 0; jt < NJT; jt++) {
        const int buf = jt & 1;

        // ---- issue next K into buf^1 ----
        if (jt + 1 < NJT) {
            const size_t krb = (size_t)(jt + 1) * BN * 512;
            const uint32_t sb = (buf ^ 1) * 32768;
#pragma unroll
            for (int i = 0; i < 8; i++) {
                int x = tid + i * THREADS;
                int kr = x >> 5, kc = x & 31;
                cpa16(su + SM_K + sb + kr * 512 + ((kc ^ (kr & 7)) << 4),
                      gkt + krb + (size_t)kr * 512 + kc * 16);
            }
        }
        asm volatile("cp.async.commit_group;" ::: "memory");

        asm volatile("cp.async.wait_group 1;" ::: "memory");
        __syncthreads();  // K(jt), V(jt) visible; prev-iter reads done

        const uint32_t khb = su + SM_K + buf * 32768;
        const uint32_t vhb = su + SM_V;

        // ==== two j32 chunks: GEMM1 -> scale -> GEMM2 each ====
#pragma unroll
        for (int ch = 0; ch < 2; ch++) {
            // ---- mask (this chunk, m32 x j32) ----
            float2 mk0[2][4], mk1[2][4];
#pragma unroll
            for (int mt = 0; mt < 2; mt++) {
                const float* mp =
                    mbase + (size_t)(m0 + mt * 16 + g) * S_LEN + jt * BN + ch * 32 + c * 2;
#pragma unroll
                for (int nt = 0; nt < 4; nt++) {
                    mk0[mt][nt] = *(const float2*)(mp + nt * 8);
                    mk1[mt][nt] = *(const float2*)(mp + 8 * S_LEN + nt * 8);
                }
            }

            // ---- GEMM1: S[m32][j32] = Q @ K^T (tf32), K-frags shared across mt ----
            float sacc[2][4][4];
#pragma unroll
            for (int mt = 0; mt < 2; mt++)
#pragma unroll
                for (int nt = 0; nt < 4; nt++)
#pragma unroll
                    for (int e = 0; e < 4; e++) sacc[mt][nt][e] = 0.f;
#pragma unroll
            for (int ksp = 0; ksp < 8; ksp++) {
                uint32_t a[2][8];
#pragma unroll
                for (int mt = 0; mt < 2; mt++) {
                    int qrow = m0 + mt * 16 + aro;
                    ldmx4(a[mt][0], a[mt][1], a[mt][2], a[mt][3],
                          su + SM_Q + qrow * 512 + (((4 * ksp + acb) ^ (qrow & 7)) << 4));
                    ldmx4(a[mt][4], a[mt][5], a[mt][6], a[mt][7],
                          su + SM_Q + qrow * 512 + (((4 * ksp + 2 + acb) ^ (qrow & 7)) << 4));
                }
#pragma unroll
                for (int np = 0; np < 4; np++) {
                    int krow = ch * 32 + np * 8 + lrow;
                    uint32_t b0, b1, b2, b3;
                    ldmx4(b0, b1, b2, b3,
                          khb + krow * 512 + (((4 * ksp + bcb) ^ (krow & 7)) << 4));
#pragma unroll
                    for (int mt = 0; mt < 2; mt++) {
                        mmat(sacc[mt][np], a[mt][0], a[mt][1], a[mt][2], a[mt][3], b0, b1);
                        mmat(sacc[mt][np], a[mt][4], a[mt][5], a[mt][6], a[mt][7], b2, b3);
                    }
                }
            }

            // ---- scale: sacc *= mask (rnorm dropped: RMSNorm is row-scale invariant) ----
#pragma unroll
            for (int mt = 0; mt < 2; mt++)
#pragma unroll
                for (int nt = 0; nt < 4; nt++) {
                    sacc[mt][nt][0] *= mk0[mt][nt].x;
                    sacc[mt][nt][1] *= mk0[mt][nt].y;
                    sacc[mt][nt][2] *= mk1[mt][nt].x;
                    sacc[mt][nt][3] *= mk1[mt][nt].y;
                }

            // ---- GEMM2: O[m32][d128] += S @ V (this chunk), V-frags shared across mt ----
#pragma unroll
            for (int ktl = 0; ktl < 2; ktl++) {
                uint32_t af[2][2][4];
#pragma unroll
                for (int mt = 0; mt < 2; mt++)
#pragma unroll
                    for (int kk = 0; kk < 2; kk++) {
                        const float* s4 = sacc[mt][2 * ktl + kk];
                        float v0 = __shfl_sync(0xffffffffu, s4[0], slo);
                        float v1 = __shfl_sync(0xffffffffu, s4[1], slo);
                        float w0 = __shfl_sync(0xffffffffu, s4[0], shi);
                        float w1 = __shfl_sync(0xffffffffu, s4[1], shi);
                        float x0 = __shfl_sync(0xffffffffu, s4[2], slo);
                        float x1 = __shfl_sync(0xffffffffu, s4[3], slo);
                        float y0 = __shfl_sync(0xffffffffu, s4[2], shi);
                        float y1 = __shfl_sync(0xffffffffu, s4[3], shi);
                        af[mt][kk][0] = f2tf(codd ? v1 : v0);
                        af[mt][kk][1] = f2tf(codd ? x1 : x0);
                        af[mt][kk][2] = f2tf(codd ? w1 : w0);
                        af[mt][kk][3] = f2tf(codd ? y1 : y0);
                    }
#pragma unroll
                for (int n8 = 0; n8 < 16; n8++) {
                    int vrow = n8 * 8 + lrow;
                    uint32_t b0, b1, b2, b3;
                    ldmx4(b0, b1, b2, b3,
                          vhb + vrow * 256 +
                              (((8 * ch + 4 * ktl + bcb) ^ (vrow & 7)) << 4));
#pragma unroll
                    for (int mt = 0; mt < 2; mt++) {
                        mmat(oacc[mt][n8], af[mt][0][0], af[mt][0][1], af[mt][0][2],
                             af[mt][0][3], b0, b1);
                        mmat(oacc[mt][n8], af[mt][1][0], af[mt][1][1], af[mt][1][2],
                             af[mt][1][3], b2, b3);
                    }
                }
            }
        }

        // ---- rotate single V buffer ----
        __syncthreads();  // all V reads done
        if (jt + 1 < NJT) {
            const size_t vcbyte = (size_t)(jt + 1) * 256;
#pragma unroll
            for (int i = 0; i < 8; i++) {
                int x = tid + i * THREADS;
                int vr = x >> 4, vc = x & 15;
                cpa16(su + SM_V + vr * 256 + ((vc ^ (vr & 7)) << 4),
                      gvt + (size_t)vr * 8192 + vcbyte + vc * 16);
            }
        }
        asm volatile("cp.async.commit_group;" ::: "memory");
    }

    // ---- RMSNorm (warp-local rows) + store ----
#pragma unroll
    for (int mt = 0; mt < 2; mt++) {
        float p0 = 0.f, p1 = 0.f;
#pragma unroll
        for (int nt = 0; nt < 16; nt++) {
            p0 += oacc[mt][nt][0] * oacc[mt][nt][0] + oacc[mt][nt][1] * oacc[mt][nt][1];
            p1 += oacc[mt][nt][2] * oacc[mt][nt][2] + oacc[mt][nt][3] * oacc[mt][nt][3];
        }
        p0 += __shfl_xor_sync(0xffffffffu, p0, 1);
        p0 += __shfl_xor_sync(0xffffffffu, p0, 2);
        p1 += __shfl_xor_sync(0xffffffffu, p1, 1);
        p1 += __shfl_xor_sync(0xffffffffu, p1, 2);
        float sc0 = rsqrtf(p0 * (1.f / 128.f) + 1e-6f);
        float sc1 = rsqrtf(p1 * (1.f / 128.f) + 1e-6f);
        float* o0 = out + (bh * S_LEN + i0 + m0 + mt * 16 + g) * DHEAD + c * 2;
        float* o1 = o0 + 8 * DHEAD;
#pragma unroll
        for (int nt = 0; nt < 16; nt++) {
            *(float2*)(o0 + nt * 8) = make_float2(oacc[mt][nt][0] * sc0, oacc[mt][nt][1] * sc0);
            *(float2*)(o1 + nt * 8) = make_float2(oacc[mt][nt][2] * sc1, oacc[mt][nt][3] * sc1);
        }
    }
}

extern "C" void kernel_launch(void* const* d_in, const int* in_sizes, int n_in,
                              void* d_out, int out_size) {
    const float* q = (const float*)d_in[0];
    const float* k = (const float*)d_in[1];
    const float* v = (const float*)d_in[2];
    const float* omask = (const float*)d_in[3];
    float* out = (float*)d_out;

    cudaFuncSetAttribute(retention_mma_kernel, cudaFuncAttributeMaxDynamicSharedMemorySize,
                         SMEM_TOTAL);

    kcvt_kernel<<<NROWS * DHEAD / (512 * 4), 512>>>(k);
    vtr_kernel<<<dim3(S_LEN / 32, DHEAD / 32, BATCH * HEADS), dim3(32, 8)>>>(v);
    retention_mma_kernel<<<dim3(S_LEN / BM, HEADS, BATCH), THREADS, SMEM_TOTAL>>>(
        q, omask, out);
}

// round 16
// speedup vs baseline: 1.4716x; 1.4436x over previous
#include <cuda_runtime.h>
#include <cstdint>

#define S_LEN 2048
#define HEADS 8
#define BATCH 2
#define DHEAD 128
#define BM 128
#define BN 64
#define NJT (S_LEN / BN)
#define THREADS 256

// smem: Q stage [128][512B]=64KB (init only); K [64][512B] x2; V^T [128][256B] x2
#define SM_Q 0
#define SM_K 65536   // + buf*32768
#define SM_V 131072  // + buf*32768
#define SMEM_TOTAL 196608

#define NROWS (BATCH * HEADS * S_LEN)

__device__ uint4 g_kt[NROWS * 32];                 // K tf32, [bh*2048+j][128]
__device__ uint4 g_vt[BATCH * HEADS * 8192 * 16];  // V^T tf32, [bh*128+d][2048]

__device__ __forceinline__ uint32_t smem_u32(const void* p) {
    uint32_t a;
    asm("{ .reg .u64 t; cvta.to.shared.u64 t, %1; cvt.u32.u64 %0, t; }" : "=r"(a) : "l"(p));
    return a;
}
__device__ __forceinline__ uint32_t f2tf(float f) {
    uint32_t r;
    asm("cvt.rna.tf32.f32 %0, %1;" : "=r"(r) : "f"(f));
    return r;
}
__device__ __forceinline__ void cpa16(uint32_t dst, const void* src) {
    asm volatile("cp.async.cg.shared.global [%0], [%1], 16;" :: "r"(dst), "l"(src));
}
__device__ __forceinline__ void ldmx4(uint32_t& r0, uint32_t& r1, uint32_t& r2, uint32_t& r3,
                                      uint32_t a) {
    asm volatile("ldmatrix.sync.aligned.m8n8.x4.shared.b16 {%0,%1,%2,%3}, [%4];"
                 : "=r"(r0), "=r"(r1), "=r"(r2), "=r"(r3) : "r"(a));
}
__device__ __forceinline__ void mmat(float* c, uint32_t a0, uint32_t a1, uint32_t a2,
                                     uint32_t a3, uint32_t b0, uint32_t b1) {
    asm volatile(
        "mma.sync.aligned.m16n8k8.row.col.f32.tf32.tf32.f32 "
        "{%0,%1,%2,%3},{%4,%5,%6,%7},{%8,%9},{%0,%1,%2,%3};"
        : "+f"(c[0]), "+f"(c[1]), "+f"(c[2]), "+f"(c[3])
        : "r"(a0), "r"(a1), "r"(a2), "r"(a3), "r"(b0), "r"(b1));
}

// ---------------- prep: K fp32 -> tf32 ----------------
__global__ void kcvt_kernel(const float* __restrict__ k) {
    int gid = blockIdx.x * 512 + threadIdx.x;
    float4 f = ((const float4*)k)[gid];
    ((uint4*)g_kt)[gid] = make_uint4(f2tf(f.x), f2tf(f.y), f2tf(f.z), f2tf(f.w));
}

// ---------------- prep: V fp32 -> tf32 transposed [bh][d][j] ----------------
__global__ void vtr_kernel(const float* __restrict__ v) {
    __shared__ uint32_t t[32][33];
    int bh = blockIdx.z, j0 = blockIdx.x * 32, d0 = blockIdx.y * 32;
    const float* src = v + ((size_t)bh * S_LEN + j0) * DHEAD + d0;
#pragma unroll
    for (int i = 0; i < 4; i++)
        t[threadIdx.y + i * 8][threadIdx.x] =
            f2tf(src[(threadIdx.y + i * 8) * DHEAD + threadIdx.x]);
    __syncthreads();
    uint32_t* dst = (uint32_t*)g_vt + ((size_t)bh * DHEAD + d0) * S_LEN + j0;
#pragma unroll
    for (int i = 0; i < 4; i++)
        dst[(threadIdx.y + i * 8) * S_LEN + threadIdx.x] = t[threadIdx.x][threadIdx.y + i * 8];
}

__global__ __launch_bounds__(THREADS, 1)
void retention_mma_kernel(const float* __restrict__ q, const float* __restrict__ omask,
                          float* __restrict__ out) {
    extern __shared__ char smc[];
    const uint32_t su = smem_u32(smc);
    const int tid = threadIdx.x;
    const int wid = tid >> 5, lane = tid & 31;
    const int m0 = wid * 16;  // each warp: rows m0..m0+15, full width & full j
    const int g = lane >> 2, c = lane & 3;

    const int it = blockIdx.x, h = blockIdx.y, b = blockIdx.z;
    const int i0 = it * BM;
    const size_t bh = (size_t)(b * HEADS + h);
    const float* qbase = q + (bh * S_LEN + i0) * DHEAD;
    const float* mbase = omask + ((size_t)h * S_LEN + i0) * S_LEN;
    const char* gkt = (const char*)g_kt + bh * (S_LEN * DHEAD * 4);
    const char* gvt = (const char*)g_vt + bh * (S_LEN * DHEAD * 4);

    // ---- issue K0 + V0 (buf0) via cp.async ----
#pragma unroll
    for (int i = 0; i < 8; i++) {
        int x = tid + i * THREADS;  // 0..2047
        int kr = x >> 5, kc = x & 31;
        cpa16(su + SM_K + kr * 512 + ((kc ^ (kr & 7)) << 4), gkt + (size_t)kr * 512 + kc * 16);
        int vr = x >> 4, vc = x & 15;
        cpa16(su + SM_V + vr * 256 + ((vc ^ (vr & 7)) << 4), gvt + (size_t)vr * 8192 + vc * 16);
    }
    asm volatile("cp.async.commit_group;" ::: "memory");

    // ---- Q tile [128x128] -> tf32 stage smem ----
#pragma unroll
    for (int i = 0; i < 16; i++) {
        int x = tid + i * THREADS;
        int r = x >> 5, ch = x & 31;
        float4 f = *(const float4*)(qbase + r * DHEAD + ch * 4);
        *(uint4*)(smc + SM_Q + r * 512 + ((ch ^ (r & 7)) << 4)) =
            make_uint4(f2tf(f.x), f2tf(f.y), f2tf(f.z), f2tf(f.w));
    }
    __syncthreads();

    // ---- load Q fragments into registers (resident for whole loop) ----
    const int lrow = lane & 7;
    const int acb = lane >> 4;  // A chunk sub (0..1)
    const int aro = lrow + ((lane >> 3) & 1) * 8;
    uint32_t qf[8][8];
    {
        const int qrow = m0 + aro;
        const uint32_t qb = su + SM_Q + qrow * 512;
#pragma unroll
        for (int ksp = 0; ksp < 8; ksp++) {
            ldmx4(qf[ksp][0], qf[ksp][1], qf[ksp][2], qf[ksp][3],
                  qb + (((4 * ksp + acb) ^ (qrow & 7)) << 4));
            ldmx4(qf[ksp][4], qf[ksp][5], qf[ksp][6], qf[ksp][7],
                  qb + (((4 * ksp + 2 + acb) ^ (qrow & 7)) << 4));
        }
    }

    float oacc[16][4];
#pragma unroll
    for (int nt = 0; nt < 16; nt++)
#pragma unroll
        for (int e = 0; e < 4; e++) oacc[nt][e] = 0.f;

    const int bcb = lane >> 3;  // B chunk sub (0..3)
    const int slo = (lane & ~3) | (c >> 1);
    const int shi = (lane & ~3) | ((c >> 1) + 2);
    const bool codd = (c & 1);

    for (int jt = 0; jt < NJT; jt++) {
        const int buf = jt & 1;
        __syncthreads();  // all reads of prev-iter buffers done

        // ---- issue next K/V into buf^1 ----
        if (jt + 1 < NJT) {
            const uint32_t sb = (buf ^ 1) * 32768;
            const size_t krb = (size_t)(jt + 1) * BN * 512;
            const size_t vcbyte = (size_t)(jt + 1) * 256;
#pragma unroll
            for (int i = 0; i < 8; i++) {
                int x = tid + i * THREADS;
                int kr = x >> 5, kc = x & 31;
                cpa16(su + SM_K + sb + kr * 512 + ((kc ^ (kr & 7)) << 4),
                      gkt + krb + (size_t)kr * 512 + kc * 16);
                int vr = x >> 4, vc = x & 15;
                cpa16(su + SM_V + sb + vr * 256 + ((vc ^ (vr & 7)) << 4),
                      gvt + (size_t)vr * 8192 + vcbyte + vc * 16);
            }
        }
        asm volatile("cp.async.commit_group;" ::: "memory");

        // ---- mask prefetch (m16 x j64; rnorm dropped — RMSNorm scale-invariant) ----
        const float* mp = mbase + (size_t)(m0 + g) * S_LEN + jt * BN + c * 2;
        float2 mk0[8], mk1[8];
#pragma unroll
        for (int nt = 0; nt < 8; nt++) {
            mk0[nt] = *(const float2*)(mp + nt * 8);
            mk1[nt] = *(const float2*)(mp + 8 * S_LEN + nt * 8);
        }

        asm volatile("cp.async.wait_group 1;" ::: "memory");
        __syncthreads();  // current tiles visible

        const uint32_t khb = su + SM_K + buf * 32768;
        const uint32_t vhb = su + SM_V + buf * 32768;

        // ---- GEMM1: S[m16][j64] = Q(reg) @ K^T (tf32) ----
        float sacc[8][4];
#pragma unroll
        for (int nt = 0; nt < 8; nt++)
#pragma unroll
            for (int e = 0; e < 4; e++) sacc[nt][e] = 0.f;
#pragma unroll
        for (int ksp = 0; ksp < 8; ksp++) {
#pragma unroll
            for (int np = 0; np < 8; np++) {
                int krow = np * 8 + lrow;
                uint32_t b0, b1, b2, b3;
                ldmx4(b0, b1, b2, b3,
                      khb + krow * 512 + (((4 * ksp + bcb) ^ (krow & 7)) << 4));
                mmat(sacc[np], qf[ksp][0], qf[ksp][1], qf[ksp][2], qf[ksp][3], b0, b1);
                mmat(sacc[np], qf[ksp][4], qf[ksp][5], qf[ksp][6], qf[ksp][7], b2, b3);
            }
        }

        // ---- scale: sacc *= mask ----
#pragma unroll
        for (int nt = 0; nt < 8; nt++) {
            sacc[nt][0] *= mk0[nt].x;
            sacc[nt][1] *= mk0[nt].y;
            sacc[nt][2] *= mk1[nt].x;
            sacc[nt][3] *= mk1[nt].y;
        }

        // ---- GEMM2: O[m16][d128] += S @ V (tf32) ----
#pragma unroll
        for (int ktp = 0; ktp < 4; ktp++) {
            uint32_t af[2][4];
#pragma unroll
            for (int kk = 0; kk < 2; kk++) {
                const float* s4 = sacc[2 * ktp + kk];
                float v0 = __shfl_sync(0xffffffffu, s4[0], slo);
                float v1 = __shfl_sync(0xffffffffu, s4[1], slo);
                float w0 = __shfl_sync(0xffffffffu, s4[0], shi);
                float w1 = __shfl_sync(0xffffffffu, s4[1], shi);
                float x0 = __shfl_sync(0xffffffffu, s4[2], slo);
                float x1 = __shfl_sync(0xffffffffu, s4[3], slo);
                float y0 = __shfl_sync(0xffffffffu, s4[2], shi);
                float y1 = __shfl_sync(0xffffffffu, s4[3], shi);
                af[kk][0] = f2tf(codd ? v1 : v0);
                af[kk][1] = f2tf(codd ? x1 : x0);
                af[kk][2] = f2tf(codd ? w1 : w0);
                af[kk][3] = f2tf(codd ? y1 : y0);
            }
#pragma unroll
            for (int n8 = 0; n8 < 16; n8++) {
                int vrow = n8 * 8 + lrow;
                uint32_t b0, b1, b2, b3;
                ldmx4(b0, b1, b2, b3,
                      vhb + vrow * 256 + (((4 * ktp + bcb) ^ (vrow & 7)) << 4));
                mmat(oacc[n8], af[0][0], af[0][1], af[0][2], af[0][3], b0, b1);
                mmat(oacc[n8], af[1][0], af[1][1], af[1][2], af[1][3], b2, b3);
            }
        }
    }

    // ---- RMSNorm (warp-local rows) + store ----
    float p0 = 0.f, p1 = 0.f;
#pragma unroll
    for (int nt = 0; nt < 16; nt++) {
        p0 += oacc[nt][0] * oacc[nt][0] + oacc[nt][1] * oacc[nt][1];
        p1 += oacc[nt][2] * oacc[nt][2] + oacc[nt][3] * oacc[nt][3];
    }
    p0 += __shfl_xor_sync(0xffffffffu, p0, 1);
    p0 += __shfl_xor_sync(0xffffffffu, p0, 2);
    p1 += __shfl_xor_sync(0xffffffffu, p1, 1);
    p1 += __shfl_xor_sync(0xffffffffu, p1, 2);
    float sc0 = rsqrtf(p0 * (1.f / 128.f) + 1e-6f);
    float sc1 = rsqrtf(p1 * (1.f / 128.f) + 1e-6f);
    float* o0 = out + (bh * S_LEN + i0 + m0 + g) * DHEAD + c * 2;
    float* o1 = o0 + 8 * DHEAD;
#pragma unroll
    for (int nt = 0; nt < 16; nt++) {
        *(float2*)(o0 + nt * 8) = make_float2(oacc[nt][0] * sc0, oacc[nt][1] * sc0);
        *(float2*)(o1 + nt * 8) = make_float2(oacc[nt][2] * sc1, oacc[nt][3] * sc1);
    }
}

extern "C" void kernel_launch(void* const* d_in, const int* in_sizes, int n_in,
                              void* d_out, int out_size) {
    const float* q = (const float*)d_in[0];
    const float* k = (const float*)d_in[1];
    const float* v = (const float*)d_in[2];
    const float* omask = (const float*)d_in[3];
    float* out = (float*)d_out;

    cudaFuncSetAttribute(retention_mma_kernel, cudaFuncAttributeMaxDynamicSharedMemorySize,
                         SMEM_TOTAL);

    kcvt_kernel<<<NROWS * DHEAD / (512 * 4), 512>>>(k);
    vtr_kernel<<<dim3(S_LEN / 32, DHEAD / 32, BATCH * HEADS), dim3(32, 8)>>>(v);
    retention_mma_kernel<<<dim3(S_LEN / BM, HEADS, BATCH), THREADS, SMEM_TOTAL>>>(
        q, omask, out);
}

// round 17
// speedup vs baseline: 2.7069x; 1.8394x over previous
#include <cuda_runtime.h>
#include <cstdint>

#define S_LEN 2048
#define HEADS 8
#define BATCH 2
#define DHEAD 128
#define BM 128
#define BN 64
#define NJT (S_LEN / BN)
#define THREADS 256

// smem: Q stage [128][256B]=32KB (init only); K [64][256B] x2; V [64][256B] x2
#define SM_Q 0
#define SM_K 32768  // + buf*16384
#define SM_V 65536  // + buf*16384
#define SMEM_TOTAL 98304

#define NROWS (BATCH * HEADS * S_LEN)

__device__ uint4 g_kh[NROWS * 16];  // K fp16, [bh*2048+j][128]
__device__ uint4 g_vh[NROWS * 16];  // V fp16, [bh*2048+j][128]

__device__ __forceinline__ uint32_t smem_u32(const void* p) {
    uint32_t a;
    asm("{ .reg .u64 t; cvta.to.shared.u64 t, %1; cvt.u32.u64 %0, t; }" : "=r"(a) : "l"(p));
    return a;
}
__device__ __forceinline__ uint32_t f2h2(float lo, float hi) {
    uint32_t r;
    asm("cvt.rn.f16x2.f32 %0, %1, %2;" : "=r"(r) : "f"(hi), "f"(lo));
    return r;
}
__device__ __forceinline__ void cpa16(uint32_t dst, const void* src) {
    asm volatile("cp.async.cg.shared.global [%0], [%1], 16;" :: "r"(dst), "l"(src));
}
__device__ __forceinline__ void ldmx4(uint32_t& r0, uint32_t& r1, uint32_t& r2, uint32_t& r3,
                                      uint32_t a) {
    asm volatile("ldmatrix.sync.aligned.m8n8.x4.shared.b16 {%0,%1,%2,%3}, [%4];"
                 : "=r"(r0), "=r"(r1), "=r"(r2), "=r"(r3) : "r"(a));
}
__device__ __forceinline__ void ldmx4t(uint32_t& r0, uint32_t& r1, uint32_t& r2, uint32_t& r3,
                                       uint32_t a) {
    asm volatile("ldmatrix.sync.aligned.m8n8.x4.trans.shared.b16 {%0,%1,%2,%3}, [%4];"
                 : "=r"(r0), "=r"(r1), "=r"(r2), "=r"(r3) : "r"(a));
}
__device__ __forceinline__ void mmah(float* c, const uint32_t* a, uint32_t b0, uint32_t b1) {
    asm volatile(
        "mma.sync.aligned.m16n8k16.row.col.f32.f16.f16.f32 "
        "{%0,%1,%2,%3},{%4,%5,%6,%7},{%8,%9},{%0,%1,%2,%3};"
        : "+f"(c[0]), "+f"(c[1]), "+f"(c[2]), "+f"(c[3])
        : "r"(a[0]), "r"(a[1]), "r"(a[2]), "r"(a[3]), "r"(b0), "r"(b1));
}

// ---------------- prep: K,V fp32 -> fp16 ----------------
__global__ void cvt_kernel(const float* __restrict__ k, const float* __restrict__ v) {
    const float* src = blockIdx.y ? v : k;
    uint2* dst = (uint2*)(blockIdx.y ? g_vh : g_kh);
    int gid = blockIdx.x * 512 + threadIdx.x;
    float4 f = ((const float4*)src)[gid];
    dst[gid] = make_uint2(f2h2(f.x, f.y), f2h2(f.z, f.w));
}

__global__ __launch_bounds__(THREADS, 1)
void retention_mma_kernel(const float* __restrict__ q, const float* __restrict__ omask,
                          float* __restrict__ out) {
    extern __shared__ char smc[];
    const uint32_t su = smem_u32(smc);
    const int tid = threadIdx.x;
    const int wid = tid >> 5, lane = tid & 31;
    const int m0 = wid * 16;  // each warp: rows m0..m0+15, full width & full j
    const int g = lane >> 2, c = lane & 3;

    const int it = blockIdx.x, h = blockIdx.y, b = blockIdx.z;
    const int i0 = it * BM;
    const size_t bh = (size_t)(b * HEADS + h);
    const float* qbase = q + (bh * S_LEN + i0) * DHEAD;
    const float* mbase = omask + ((size_t)h * S_LEN + i0) * S_LEN;
    const char* gkh = (const char*)g_kh + bh * (S_LEN * 256);
    const char* gvh = (const char*)g_vh + bh * (S_LEN * 256);

    // ---- issue K0 + V0 (buf0) via cp.async ----
#pragma unroll
    for (int i = 0; i < 4; i++) {
        int x = tid + i * THREADS;  // 0..1023
        int r = x >> 4, ch = x & 15;
        uint32_t sw = r * 256 + ((ch ^ (r & 7)) << 4);
        size_t go = (size_t)r * 256 + ch * 16;
        cpa16(su + SM_K + sw, gkh + go);
        cpa16(su + SM_V + sw, gvh + go);
    }
    asm volatile("cp.async.commit_group;" ::: "memory");

    // ---- Q tile [128x128] -> fp16 stage smem ----
#pragma unroll
    for (int i = 0; i < 16; i++) {
        int x = tid + i * THREADS;  // 0..4095
        int r = x >> 5, c4 = (x & 31) << 2;
        float4 f = *(const float4*)(qbase + r * DHEAD + c4);
        int off = r * 256 + ((((c4 >> 3)) ^ (r & 7)) << 4) + (c4 & 7) * 2;
        *(uint2*)(smc + SM_Q + off) = make_uint2(f2h2(f.x, f.y), f2h2(f.z, f.w));
    }
    __syncthreads();

    // ---- load Q fragments into registers (resident for whole loop) ----
    uint32_t qf[8][4];
    {
        const int qrow = m0 + (lane & 15);
        const uint32_t qb = su + SM_Q + qrow * 256;
#pragma unroll
        for (int ks = 0; ks < 8; ks++)
            ldmx4(qf[ks][0], qf[ks][1], qf[ks][2], qf[ks][3],
                  qb + (((2 * ks + (lane >> 4)) ^ (qrow & 7)) << 4));
    }

    float oacc[16][4];
#pragma unroll
    for (int nt = 0; nt < 16; nt++)
#pragma unroll
        for (int e = 0; e < 4; e++) oacc[nt][e] = 0.f;

    const int krow_b = (lane & 7) + ((lane >> 4) << 3);

    for (int jt = 0; jt < NJT; jt++) {
        const int buf = jt & 1;
        __syncthreads();  // all reads of prev-iter buffers done

        // ---- issue next K/V into buf^1 ----
        if (jt + 1 < NJT) {
            const uint32_t sb = (buf ^ 1) * 16384;
            const size_t rb = (size_t)(jt + 1) * BN * 256;
#pragma unroll
            for (int i = 0; i < 4; i++) {
                int x = tid + i * THREADS;
                int r = x >> 4, ch = x & 15;
                uint32_t sw = r * 256 + ((ch ^ (r & 7)) << 4) + sb;
                size_t go = rb + (size_t)r * 256 + ch * 16;
                cpa16(su + SM_K + sw, gkh + go);
                cpa16(su + SM_V + sw, gvh + go);
            }
        }
        asm volatile("cp.async.commit_group;" ::: "memory");

        // ---- mask prefetch (m16 x j64; rnorm dropped — RMSNorm scale-invariant) ----
        const float* mp = mbase + (size_t)(m0 + g) * S_LEN + jt * BN + c * 2;
        float2 mk0[8], mk1[8];
#pragma unroll
        for (int nt = 0; nt < 8; nt++) {
            mk0[nt] = *(const float2*)(mp + nt * 8);
            mk1[nt] = *(const float2*)(mp + 8 * S_LEN + nt * 8);
        }

        asm volatile("cp.async.wait_group 1;" ::: "memory");
        __syncthreads();  // current tiles visible

        const uint32_t khb = su + SM_K + buf * 16384;
        const uint32_t vhb = su + SM_V + buf * 16384;

        // ---- GEMM1: S[m16][j64] = Q(reg) @ K^T (fp16) ----
        float sacc[8][4];
#pragma unroll
        for (int nt = 0; nt < 8; nt++)
#pragma unroll
            for (int e = 0; e < 4; e++) sacc[nt][e] = 0.f;
#pragma unroll
        for (int ks = 0; ks < 8; ks++) {
#pragma unroll
            for (int np = 0; np < 4; np++) {
                int krow = np * 16 + krow_b;
                uint32_t koff =
                    krow * 256 + (((2 * ks + ((lane >> 3) & 1)) ^ (krow & 7)) << 4);
                uint32_t b0, b1, b2, b3;
                ldmx4(b0, b1, b2, b3, khb + koff);
                mmah(sacc[2 * np], qf[ks], b0, b1);
                mmah(sacc[2 * np + 1], qf[ks], b2, b3);
            }
        }

        // ---- scale: sacc *= mask ----
#pragma unroll
        for (int nt = 0; nt < 8; nt++) {
            sacc[nt][0] *= mk0[nt].x;
            sacc[nt][1] *= mk0[nt].y;
            sacc[nt][2] *= mk1[nt].x;
            sacc[nt][3] *= mk1[nt].y;
        }

        // ---- GEMM2: O[m16][d128] += S @ V (fp16, B via ldmatrix.trans) ----
#pragma unroll
        for (int kt = 0; kt < 4; kt++) {
            uint32_t af[4];
            af[0] = f2h2(sacc[2 * kt][0], sacc[2 * kt][1]);
            af[1] = f2h2(sacc[2 * kt][2], sacc[2 * kt][3]);
            af[2] = f2h2(sacc[2 * kt + 1][0], sacc[2 * kt + 1][1]);
            af[3] = f2h2(sacc[2 * kt + 1][2], sacc[2 * kt + 1][3]);
            const int vrow = kt * 16 + (lane & 15);
#pragma unroll
            for (int np = 0; np < 8; np++) {
                uint32_t voff = vrow * 256 + (((2 * np + (lane >> 4)) ^ (vrow & 7)) << 4);
                uint32_t b0, b1, b2, b3;
                ldmx4t(b0, b1, b2, b3, vhb + voff);
                mmah(oacc[2 * np], af, b0, b1);
                mmah(oacc[2 * np + 1], af, b2, b3);
            }
        }
    }

    // ---- RMSNorm (warp-local rows) + store ----
    float p0 = 0.f, p1 = 0.f;
#pragma unroll
    for (int nt = 0; nt < 16; nt++) {
        p0 += oacc[nt][0] * oacc[nt][0] + oacc[nt][1] * oacc[nt][1];
        p1 += oacc[nt][2] * oacc[nt][2] + oacc[nt][3] * oacc[nt][3];
    }
    p0 += __shfl_xor_sync(0xffffffffu, p0, 1);
    p0 += __shfl_xor_sync(0xffffffffu, p0, 2);
    p1 += __shfl_xor_sync(0xffffffffu, p1, 1);
    p1 += __shfl_xor_sync(0xffffffffu, p1, 2);
    float sc0 = rsqrtf(p0 * (1.f / 128.f) + 1e-6f);
    float sc1 = rsqrtf(p1 * (1.f / 128.f) + 1e-6f);
    float* o0 = out + (bh * S_LEN + i0 + m0 + g) * DHEAD + c * 2;
    float* o1 = o0 + 8 * DHEAD;
#pragma unroll
    for (int nt = 0; nt < 16; nt++) {
        *(float2*)(o0 + nt * 8) = make_float2(oacc[nt][0] * sc0, oacc[nt][1] * sc0);
        *(float2*)(o1 + nt * 8) = make_float2(oacc[nt][2] * sc1, oacc[nt][3] * sc1);
    }
}

extern "C" void kernel_launch(void* const* d_in, const int* in_sizes, int n_in,
                              void* d_out, int out_size) {
    const float* q = (const float*)d_in[0];
    const float* k = (const float*)d_in[1];
    const float* v = (const float*)d_in[2];
    const float* omask = (const float*)d_in[3];
    float* out = (float*)d_out;

    cudaFuncSetAttribute(retention_mma_kernel, cudaFuncAttributeMaxDynamicSharedMemorySize,
                         SMEM_TOTAL);

    cvt_kernel<<<dim3(NROWS * DHEAD / (512 * 4), 2), 512>>>(k, v);
    retention_mma_kernel<<<dim3(S_LEN / BM, HEADS, BATCH), THREADS, SMEM_TOTAL>>>(
        q, omask, out);
}